// round 2
// baseline (speedup 1.0000x reference)
#include <cuda_runtime.h>
#include <math.h>

#define SS 512
#define BB 256
#define EE 256
#define HH 256
#define GG 1024   // 4*H
#define TT 32

// Scratch (device globals: allocation-free contract)
__device__ float g_gx[2][SS][BB][GG];      // pre-activations (input proj + biases)  ~1 GB
__device__ float g_h[2][SS + 1][BB][HH];   // hidden states, slot 0 = zeros          ~269 MB
__device__ float g_c[2][BB][HH];           // cell state
__device__ float g_emit[BB][SS][TT];       // emission scores

// ---------------------------------------------------------------------------
// Zero the per-launch mutable state (cell state + h slot 0)
// ---------------------------------------------------------------------------
__global__ void init_kernel() {
    int idx = blockIdx.x * blockDim.x + threadIdx.x;
    if (idx < 2 * BB * HH) {
        ((float*)g_c)[idx] = 0.f;
        int dir = idx >> 16;          // 65536 per dir
        int rem = idx & 65535;
        g_h[dir][0][rem >> 8][rem & 255] = 0.f;
    }
}

// ---------------------------------------------------------------------------
// Input projection GEMM with fused embedding gather:
//   gx[dir][s][b][g] = sum_e embed[row(dir,b,s)][e] * W_ih[dir][g][e] + b_ih[g] + b_hh[g]
// M = S*B (m = s*256 + b), N = 1024, K = 256. Tiles: 64x64xK32, 256 thr, 4x4 micro.
// ---------------------------------------------------------------------------
__global__ __launch_bounds__(256) void gemm_inproj(
    const float* __restrict__ embed,
    const float* __restrict__ Wf, const float* __restrict__ Wb,
    const float* __restrict__ bih_f, const float* __restrict__ bhh_f,
    const float* __restrict__ bih_b, const float* __restrict__ bhh_b,
    const int* __restrict__ sent, const int* __restrict__ lens)
{
    const int dir = blockIdx.z;
    const int m0 = blockIdx.x * 64;
    const int n0 = blockIdx.y * 64;
    const int s  = m0 >> 8;          // each m-tile covers a single time step
    const int bfirst = m0 & 255;
    if (s >= lens[bfirst]) return;   // lengths sorted descending -> tile max at bfirst

    __shared__ float At[32][68];
    __shared__ float Wt[32][68];
    __shared__ int rowid[64];

    const int tid = threadIdx.x;
    if (tid < 64) {
        int b = bfirst + tid;
        int len = lens[b];
        int ss = s;
        if (dir == 1) ss = (s < len) ? (len - 1 - s) : s;   // reversed gather
        rowid[tid] = sent[b * SS + ss];
    }
    __syncthreads();

    const float* __restrict__ W = dir ? Wb : Wf;
    const int tx = tid & 15, ty = tid >> 4;
    const int mi = tid >> 2, v = tid & 3;

    const float* arowbase = embed + (size_t)rowid[mi] * EE;
    const float* wrowbase = W + (size_t)(n0 + mi) * EE;

    float acc[4][4] = {};
    for (int kc = 0; kc < EE; kc += 32) {
        float4 a0 = *(const float4*)(arowbase + kc + v * 4);
        float4 a1 = *(const float4*)(arowbase + kc + 16 + v * 4);
        float4 w0 = *(const float4*)(wrowbase + kc + v * 4);
        float4 w1 = *(const float4*)(wrowbase + kc + 16 + v * 4);
        __syncthreads();
        At[v*4+0][mi] = a0.x; At[v*4+1][mi] = a0.y; At[v*4+2][mi] = a0.z; At[v*4+3][mi] = a0.w;
        At[16+v*4+0][mi] = a1.x; At[16+v*4+1][mi] = a1.y; At[16+v*4+2][mi] = a1.z; At[16+v*4+3][mi] = a1.w;
        Wt[v*4+0][mi] = w0.x; Wt[v*4+1][mi] = w0.y; Wt[v*4+2][mi] = w0.z; Wt[v*4+3][mi] = w0.w;
        Wt[16+v*4+0][mi] = w1.x; Wt[16+v*4+1][mi] = w1.y; Wt[16+v*4+2][mi] = w1.z; Wt[16+v*4+3][mi] = w1.w;
        __syncthreads();
        #pragma unroll
        for (int k = 0; k < 32; k++) {
            float4 af = *(const float4*)&At[k][ty * 4];
            float4 wf = *(const float4*)&Wt[k][tx * 4];
            float a_[4] = {af.x, af.y, af.z, af.w};
            float w_[4] = {wf.x, wf.y, wf.z, wf.w};
            #pragma unroll
            for (int r = 0; r < 4; r++)
                #pragma unroll
                for (int c = 0; c < 4; c++)
                    acc[r][c] += a_[r] * w_[c];
        }
    }

    const float* bi = dir ? bih_b : bih_f;
    const float* bh = dir ? bhh_b : bhh_f;
    int n = n0 + tx * 4;
    float4 bv;
    bv.x = bi[n] + bh[n]; bv.y = bi[n+1] + bh[n+1];
    bv.z = bi[n+2] + bh[n+2]; bv.w = bi[n+3] + bh[n+3];
    float* gxp = &g_gx[dir][0][0][0];
    #pragma unroll
    for (int r = 0; r < 4; r++) {
        int m = m0 + ty * 4 + r;
        float4 o;
        o.x = acc[r][0] + bv.x; o.y = acc[r][1] + bv.y;
        o.z = acc[r][2] + bv.z; o.w = acc[r][3] + bv.w;
        *(float4*)(gxp + (size_t)m * GG + n) = o;
    }
}

// ---------------------------------------------------------------------------
// One LSTM time step (both directions in grid.z). Per block: 64 batch x 16
// hidden-units x 4 gates (gate-strided N tile so the gate nonlinearity can be
// fused in-block). GEMM: M=64(batch), N=64(cols), K=256(hprev).
// ---------------------------------------------------------------------------
__global__ __launch_bounds__(256) void lstm_step(
    int s,
    const float* __restrict__ Whh_f, const float* __restrict__ Whh_b,
    const int* __restrict__ lens)
{
    const int dir = blockIdx.z;
    const int b0 = blockIdx.y * 64;
    const int jt = blockIdx.x;       // 0..15 hidden-unit tile
    if (s >= lens[b0]) return;

    __shared__ float At[32][68];
    __shared__ float Wt[32][68];
    __shared__ float Cs[64][68];

    const int tid = threadIdx.x;
    const int tx = tid & 15, ty = tid >> 4;
    const int mi = tid >> 2, v = tid & 3;

    const float* __restrict__ W = dir ? Whh_b : Whh_f;
    const float* hprev = &g_h[dir][s][0][0];
    const float* gxs   = &g_gx[dir][s][0][0];

    // local column ni -> global gate column: g = ni>>4, jj = ni&15
    const int nloc0 = tx * 4;
    const int ncol0 = ((nloc0 >> 4) << 8) + jt * 16 + (nloc0 & 15);

    float acc[4][4];
    #pragma unroll
    for (int r = 0; r < 4; r++) {
        float4 gv = *(const float4*)(gxs + (size_t)(b0 + ty * 4 + r) * GG + ncol0);
        acc[r][0] = gv.x; acc[r][1] = gv.y; acc[r][2] = gv.z; acc[r][3] = gv.w;
    }

    const int nrow = ((mi >> 4) << 8) + jt * 16 + (mi & 15);
    const float* arowbase = hprev + (size_t)(b0 + mi) * HH;
    const float* wrowbase = W + (size_t)nrow * HH;

    for (int kc = 0; kc < HH; kc += 32) {
        float4 a0 = *(const float4*)(arowbase + kc + v * 4);
        float4 a1 = *(const float4*)(arowbase + kc + 16 + v * 4);
        float4 w0 = *(const float4*)(wrowbase + kc + v * 4);
        float4 w1 = *(const float4*)(wrowbase + kc + 16 + v * 4);
        __syncthreads();
        At[v*4+0][mi] = a0.x; At[v*4+1][mi] = a0.y; At[v*4+2][mi] = a0.z; At[v*4+3][mi] = a0.w;
        At[16+v*4+0][mi] = a1.x; At[16+v*4+1][mi] = a1.y; At[16+v*4+2][mi] = a1.z; At[16+v*4+3][mi] = a1.w;
        Wt[v*4+0][mi] = w0.x; Wt[v*4+1][mi] = w0.y; Wt[v*4+2][mi] = w0.z; Wt[v*4+3][mi] = w0.w;
        Wt[16+v*4+0][mi] = w1.x; Wt[16+v*4+1][mi] = w1.y; Wt[16+v*4+2][mi] = w1.z; Wt[16+v*4+3][mi] = w1.w;
        __syncthreads();
        #pragma unroll
        for (int k = 0; k < 32; k++) {
            float4 af = *(const float4*)&At[k][ty * 4];
            float4 wf = *(const float4*)&Wt[k][tx * 4];
            float a_[4] = {af.x, af.y, af.z, af.w};
            float w_[4] = {wf.x, wf.y, wf.z, wf.w};
            #pragma unroll
            for (int r = 0; r < 4; r++)
                #pragma unroll
                for (int c = 0; c < 4; c++)
                    acc[r][c] += a_[r] * w_[c];
        }
    }

    // stage GEMM result so each thread can pick up all 4 gates of a (b, j)
    #pragma unroll
    for (int r = 0; r < 4; r++)
        *(float4*)&Cs[ty * 4 + r][tx * 4] = make_float4(acc[r][0], acc[r][1], acc[r][2], acc[r][3]);
    __syncthreads();

    float* hout = &g_h[dir][s + 1][0][0];
    float* cptr = &g_c[dir][0][0];
    #pragma unroll
    for (int r = 0; r < 4; r++) {
        int p = tid + 256 * r;           // 1024 (b,j) pairs
        int bl = p >> 4, jj = p & 15;
        float gi = Cs[bl][jj];
        float gf = Cs[bl][16 + jj];
        float gg = Cs[bl][32 + jj];
        float go = Cs[bl][48 + jj];
        int b = b0 + bl;
        int jcol = jt * 16 + jj;
        size_t off = (size_t)b * HH + jcol;
        float cp = cptr[off];
        float si = 1.f / (1.f + expf(-gi));
        float sf = 1.f / (1.f + expf(-gf));
        float so = 1.f / (1.f + expf(-go));
        float cn = sf * cp + si * tanhf(gg);
        float hn = so * tanhf(cn);
        cptr[off] = cn;
        hout[off] = hn;
    }
}

// ---------------------------------------------------------------------------
// emit[b][s][t] = b_out[t] + h_f[s] . W_out[t][0:256] + h_b[len-1-s] . W_out[t][256:512]
// Only for s < len[b] (everything else is masked out downstream).
// Block: one b, 8 s-values, 32 tags. 256 threads.
// ---------------------------------------------------------------------------
__global__ __launch_bounds__(256) void emit_kernel(
    const float* __restrict__ Wout, const float* __restrict__ bout,
    const int* __restrict__ lens)
{
    int b = blockIdx.x;
    int s0 = blockIdx.y * 8;
    int len = lens[b];
    if (s0 >= len) return;

    __shared__ float hbuf[8][512];
    __shared__ float Wt[32][65];

    int tid = threadIdx.x;
    for (int idx = tid; idx < 8 * 512; idx += 256) {
        int sl = idx >> 9, k = idx & 511;
        int s = s0 + sl;
        float vv = 0.f;
        if (s < len)
            vv = (k < 256) ? g_h[0][s + 1][b][k]
                           : g_h[1][len - s][b][k - 256];
        hbuf[sl][k] = vv;
    }

    int t  = tid & 31;
    int sl = tid >> 5;
    float acc = 0.f;
    for (int kc = 0; kc < 512; kc += 64) {
        __syncthreads();
        for (int idx = tid; idx < 32 * 64; idx += 256) {
            int tt = idx >> 6, kk = idx & 63;
            Wt[tt][kk] = Wout[tt * 512 + kc + kk];
        }
        __syncthreads();
        #pragma unroll
        for (int k = 0; k < 64; k++)
            acc += hbuf[sl][kc + k] * Wt[t][k];
    }
    int s = s0 + sl;
    if (s < len)
        g_emit[b][s][t] = acc + bout[t];
}

// ---------------------------------------------------------------------------
// Per-batch CRF: real path score + forward algorithm (logsumexp) + output.
// One warp per batch element.
// ---------------------------------------------------------------------------
__global__ void crf_kernel(
    const float* __restrict__ trans,
    const int* __restrict__ tags,
    const int* __restrict__ lens,
    float* __restrict__ out)
{
    int b = blockIdx.x;
    int j = threadIdx.x;   // 0..31
    __shared__ float tr[32][33];
    __shared__ float alpha[32];

    int len = lens[b];
    for (int idx = j; idx < 1024; idx += 32)
        tr[idx >> 5][idx & 31] = trans[idx];
    __syncwarp();

    const int* tg = tags + b * SS;
    const float* em = &g_emit[b][0][0];

    // real path score (parallel over s, warp reduce)
    float rs = 0.f;
    for (int s = j; s < len; s += 32) {
        int t1 = tg[s];
        float v = em[s * 32 + t1];
        if (s > 0) v += tr[tg[s - 1]][t1];
        rs += v;
    }
    #pragma unroll
    for (int o = 16; o; o >>= 1) rs += __shfl_xor_sync(0xffffffffu, rs, o);

    // forward algorithm
    alpha[j] = em[j];   // emit[b][0][j]
    __syncwarp();
    for (int s = 1; s < len; s++) {
        float m = -1e30f;
        #pragma unroll
        for (int i = 0; i < 32; i++) m = fmaxf(m, alpha[i] + tr[i][j]);
        float sum = 0.f;
        #pragma unroll
        for (int i = 0; i < 32; i++) sum += expf(alpha[i] + tr[i][j] - m);
        float nj = m + logf(sum) + em[s * 32 + j];
        __syncwarp();
        alpha[j] = nj;
        __syncwarp();
    }

    float a = alpha[j];
    float m = a;
    #pragma unroll
    for (int o = 16; o; o >>= 1) m = fmaxf(m, __shfl_xor_sync(0xffffffffu, m, o));
    float e = expf(a - m);
    #pragma unroll
    for (int o = 16; o; o >>= 1) e += __shfl_xor_sync(0xffffffffu, e, o);
    float logz = m + logf(e);
    if (j == 0) out[b] = logz - rs;
}

// ---------------------------------------------------------------------------
extern "C" void kernel_launch(void* const* d_in, const int* in_sizes, int n_in,
                              void* d_out, int out_size)
{
    const float* embed = (const float*)d_in[0];
    const float* Wih_f = (const float*)d_in[1];
    const float* Whh_f = (const float*)d_in[2];
    const float* bih_f = (const float*)d_in[3];
    const float* bhh_f = (const float*)d_in[4];
    const float* Wih_b = (const float*)d_in[5];
    const float* Whh_b = (const float*)d_in[6];
    const float* bih_b = (const float*)d_in[7];
    const float* bhh_b = (const float*)d_in[8];
    const float* Wout  = (const float*)d_in[9];
    const float* bout  = (const float*)d_in[10];
    const float* trans = (const float*)d_in[11];
    const int* sent = (const int*)d_in[12];
    const int* tags = (const int*)d_in[13];
    const int* lens = (const int*)d_in[14];
    float* out = (float*)d_out;

    init_kernel<<<512, 256>>>();

    dim3 g1(2048, 16, 2);
    gemm_inproj<<<g1, 256>>>(embed, Wih_f, Wih_b, bih_f, bhh_f, bih_b, bhh_b, sent, lens);

    dim3 gs(16, 4, 2);
    for (int s = 0; s < SS; s++)
        lstm_step<<<gs, 256>>>(s, Whh_f, Whh_b, lens);

    dim3 ge(256, 64);
    emit_kernel<<<ge, 256>>>(Wout, bout, lens);

    crf_kernel<<<256, 32>>>(trans, tags, lens, out);
}

// round 3
// speedup vs baseline: 1.4944x; 1.4944x over previous
#include <cuda_runtime.h>
#include <math.h>
#include <stdint.h>

#define SS 512
#define BB 256
#define EE 256
#define HH 256
#define GG 1024   // 4*H
#define TT 32

// Scratch (device globals: allocation-free contract)
__device__ float g_gx[2][SS][BB][GG];      // pre-activations (input proj + biases)
__device__ float g_h[2][SS + 1][BB][HH];   // hidden states, slot 0 = zeros
__device__ float g_emit[BB][SS][TT];       // emission scores
__device__ unsigned int g_bar[2];          // per-direction step barrier

// ---------------------------------------------------------------------------
__device__ __forceinline__ uint32_t f2tf32(float x) {
    uint32_t u;
    asm("cvt.rna.tf32.f32 %0, %1;" : "=r"(u) : "f"(x));
    return u;
}

__device__ __forceinline__ void mma_tf32(float d[4], const uint32_t a[4], const uint32_t b[2]) {
    asm volatile(
        "mma.sync.aligned.m16n8k8.row.col.f32.tf32.tf32.f32 "
        "{%0,%1,%2,%3}, {%4,%5,%6,%7}, {%8,%9}, {%0,%1,%2,%3};\n"
        : "+f"(d[0]), "+f"(d[1]), "+f"(d[2]), "+f"(d[3])
        : "r"(a[0]), "r"(a[1]), "r"(a[2]), "r"(a[3]), "r"(b[0]), "r"(b[1]));
}

// ---------------------------------------------------------------------------
// Zero per-launch mutable state: h slot 0 and the step barriers.
// ---------------------------------------------------------------------------
__global__ void init_kernel() {
    int idx = blockIdx.x * blockDim.x + threadIdx.x;
    if (idx < 2 * BB * HH) {
        int dir = idx >> 16;
        int rem = idx & 65535;
        g_h[dir][0][rem >> 8][rem & 255] = 0.f;
    }
    if (idx < 2) g_bar[idx] = 0u;
}

// ---------------------------------------------------------------------------
// Input projection with fused embedding gather (TF32 tensor cores):
//   gx[dir][s][b][n] = sum_e embed[row][e] * W_ih[n][e] + b_ih[n] + b_hh[n]
// Block tile: 64 (batch rows at fixed s) x 128 (gate cols), K=256 fully smem-
// resident. 256 threads = 8 warps, warp tile 16x64 (wm 0..3, wn 0..1).
// ---------------------------------------------------------------------------
#define INP_SMEM ((64 * 260 + 128 * 260) * 4)

__global__ __launch_bounds__(256) void gemm_inproj_tc(
    const float* __restrict__ embed,
    const float* __restrict__ Wf, const float* __restrict__ Wb,
    const float* __restrict__ bih_f, const float* __restrict__ bhh_f,
    const float* __restrict__ bih_b, const float* __restrict__ bhh_b,
    const int* __restrict__ sent, const int* __restrict__ lens)
{
    extern __shared__ float sm[];
    float* As = sm;             // [64][260]
    float* Ws = sm + 64 * 260;  // [128][260]
    __shared__ int rowid[64];

    const int dir = blockIdx.z;
    const int m0 = blockIdx.x * 64;
    const int n0 = blockIdx.y * 128;
    const int s  = m0 >> 8;
    const int bf = m0 & 255;
    if (s >= lens[bf]) return;   // lengths sorted desc

    const int tid = threadIdx.x;
    if (tid < 64) {
        int b = bf + tid;
        int len = lens[b];
        int ss = (dir == 1 && s < len) ? (len - 1 - s) : s;
        rowid[tid] = sent[b * SS + ss];
    }
    __syncthreads();

    // A gather (tf32)
    for (int idx = tid; idx < 64 * 64; idx += 256) {
        int r = idx >> 6, q = (idx & 63) * 4;
        float4 v = *(const float4*)(embed + (size_t)rowid[r] * EE + q);
        float* dst = As + r * 260 + q;
        dst[0] = __uint_as_float(f2tf32(v.x));
        dst[1] = __uint_as_float(f2tf32(v.y));
        dst[2] = __uint_as_float(f2tf32(v.z));
        dst[3] = __uint_as_float(f2tf32(v.w));
    }
    // W tile (tf32)
    const float* __restrict__ W = dir ? Wb : Wf;
    for (int idx = tid; idx < 128 * 64; idx += 256) {
        int c = idx >> 6, q = (idx & 63) * 4;
        float4 w = *(const float4*)(W + (size_t)(n0 + c) * EE + q);
        float* dst = Ws + c * 260 + q;
        dst[0] = __uint_as_float(f2tf32(w.x));
        dst[1] = __uint_as_float(f2tf32(w.y));
        dst[2] = __uint_as_float(f2tf32(w.z));
        dst[3] = __uint_as_float(f2tf32(w.w));
    }
    __syncthreads();

    const int lane = tid & 31, wid = tid >> 5;
    const int wm = wid & 3, wn = wid >> 2;
    const int lr = lane >> 2, lc = lane & 3;

    float acc[8][4];
    #pragma unroll
    for (int i = 0; i < 8; i++)
        #pragma unroll
        for (int j = 0; j < 4; j++) acc[i][j] = 0.f;

    const uint32_t* au = (const uint32_t*)As;
    const uint32_t* wu = (const uint32_t*)Ws;
    const int arow = (wm * 16 + lr) * 260;

    #pragma unroll 2
    for (int kc = 0; kc < 256; kc += 8) {
        uint32_t a[4];
        a[0] = au[arow + kc + lc];
        a[1] = au[arow + 8 * 260 + kc + lc];
        a[2] = au[arow + kc + lc + 4];
        a[3] = au[arow + 8 * 260 + kc + lc + 4];
        #pragma unroll
        for (int nf = 0; nf < 8; nf++) {
            int cc = wn * 64 + nf * 8 + lr;
            uint32_t b[2];
            b[0] = wu[cc * 260 + kc + lc];
            b[1] = wu[cc * 260 + kc + lc + 4];
            mma_tf32(acc[nf], a, b);
        }
    }

    const float* bi = dir ? bih_b : bih_f;
    const float* bh = dir ? bhh_b : bhh_f;
    float* gxp = &g_gx[dir][0][0][0];
    const int row = m0 + wm * 16 + lr;
    #pragma unroll
    for (int nf = 0; nf < 8; nf++) {
        int n = n0 + wn * 64 + nf * 8 + lc * 2;
        float b0v = bi[n] + bh[n];
        float b1v = bi[n + 1] + bh[n + 1];
        *(float2*)(gxp + (size_t)row * GG + n) =
            make_float2(acc[nf][0] + b0v, acc[nf][1] + b1v);
        *(float2*)(gxp + (size_t)(row + 8) * GG + n) =
            make_float2(acc[nf][2] + b0v, acc[nf][3] + b1v);
    }
}

// ---------------------------------------------------------------------------
// Persistent bidirectional LSTM. 128 blocks = 2 dirs x 8 batch-tiles(32) x
// 8 j-tiles(32 hidden units -> 128 gate cols). W_hh tile stays in smem for all
// 512 steps; cell state lives in registers. Steps synchronize through a
// per-direction device-wide barrier (64 blocks each).
// ---------------------------------------------------------------------------
#define LSTM_SMEM ((128 * 260 + 32 * 260 + 32 * 132) * 4)

__global__ __launch_bounds__(256) void lstm_persist(
    const float* __restrict__ Whh_f, const float* __restrict__ Whh_b,
    const int* __restrict__ lens)
{
    extern __shared__ float sm[];
    float* Ws = sm;                       // [128][260] tf32 weights
    float* hs = sm + 128 * 260;           // [32][260] tf32 h_prev tile
    float* st = hs + 32 * 260;            // [32][132] gate staging

    const int tid = threadIdx.x;
    const int dir = blockIdx.x >> 6;
    const int blk = blockIdx.x & 63;
    const int mb = blk >> 3;              // batch tile
    const int jt = blk & 7;               // hidden-unit tile
    const int b0 = mb * 32;
    const int lenmax = lens[b0];          // max length in this tile (sorted desc)

    // Load weights once (tf32). Block col c -> gate g = c>>5, j = jt*32 + (c&31)
    const float* __restrict__ W = dir ? Whh_b : Whh_f;
    for (int idx = tid; idx < 128 * 64; idx += 256) {
        int c = idx >> 6, q = (idx & 63) * 4;
        int n = ((c >> 5) << 8) + jt * 32 + (c & 31);
        float4 w = *(const float4*)(W + (size_t)n * HH + q);
        float* dst = Ws + c * 260 + q;
        dst[0] = __uint_as_float(f2tf32(w.x));
        dst[1] = __uint_as_float(f2tf32(w.y));
        dst[2] = __uint_as_float(f2tf32(w.z));
        dst[3] = __uint_as_float(f2tf32(w.w));
    }

    const int lane = tid & 31, wid = tid >> 5;
    const int wm = wid >> 2;      // 0..1 : 16-row batch slab
    const int wn = wid & 3;       // 0..3 : gate
    const int lr = lane >> 2, lc = lane & 3;

    float creg[4] = {0.f, 0.f, 0.f, 0.f};  // cell state, 4 (b,j) pairs/thread

    const float* gxbase = &g_gx[dir][0][0][0];
    float* hbase = &g_h[dir][0][0][0];
    unsigned int* barp = &g_bar[dir];

    const uint32_t* hsu = (const uint32_t*)hs;
    const uint32_t* wsu = (const uint32_t*)Ws;
    const int arow = (wm * 16 + lr) * 260;

    for (int s = 0; s < SS; s++) {
        if (s < lenmax) {
            // load h_prev tile as tf32
            const float* hsrc = hbase + (size_t)s * BB * HH + (size_t)b0 * HH;
            for (int idx = tid; idx < 32 * 64; idx += 256) {
                int r = idx >> 6, q = (idx & 63) * 4;
                float4 v = *(const float4*)(hsrc + r * HH + q);
                float* dst = hs + r * 260 + q;
                dst[0] = __uint_as_float(f2tf32(v.x));
                dst[1] = __uint_as_float(f2tf32(v.y));
                dst[2] = __uint_as_float(f2tf32(v.z));
                dst[3] = __uint_as_float(f2tf32(v.w));
            }
            __syncthreads();

            float acc[4][4];
            #pragma unroll
            for (int i = 0; i < 4; i++)
                #pragma unroll
                for (int j = 0; j < 4; j++) acc[i][j] = 0.f;

            #pragma unroll 4
            for (int kc = 0; kc < 256; kc += 8) {
                uint32_t a[4];
                a[0] = hsu[arow + kc + lc];
                a[1] = hsu[arow + 8 * 260 + kc + lc];
                a[2] = hsu[arow + kc + lc + 4];
                a[3] = hsu[arow + 8 * 260 + kc + lc + 4];
                #pragma unroll
                for (int nf = 0; nf < 4; nf++) {
                    int cc = wn * 32 + nf * 8 + lr;
                    uint32_t b[2];
                    b[0] = wsu[cc * 260 + kc + lc];
                    b[1] = wsu[cc * 260 + kc + lc + 4];
                    mma_tf32(acc[nf], a, b);
                }
            }

            // stage gemm result (block cols: c = gate*32 + j_local)
            {
                int r = wm * 16 + lr;
                #pragma unroll
                for (int nf = 0; nf < 4; nf++) {
                    int c = wn * 32 + nf * 8 + lc * 2;
                    *(float2*)(st + r * 132 + c) = make_float2(acc[nf][0], acc[nf][1]);
                    *(float2*)(st + (r + 8) * 132 + c) = make_float2(acc[nf][2], acc[nf][3]);
                }
            }
            __syncthreads();

            // gate epilogue: 1024 (b,j) pairs, 4 per thread
            const float* gxs = gxbase + (size_t)s * BB * GG;
            float* hdst = hbase + (size_t)(s + 1) * BB * HH;
            #pragma unroll
            for (int r = 0; r < 4; r++) {
                int p = r * 256 + tid;
                int bl = p >> 5, jj = p & 31;
                int b = b0 + bl;
                int jcol = jt * 32 + jj;
                const float* gxrow = gxs + (size_t)b * GG + jcol;
                float gi = st[bl * 132 + jj]      + gxrow[0];
                float gf = st[bl * 132 + 32 + jj] + gxrow[256];
                float gg = st[bl * 132 + 64 + jj] + gxrow[512];
                float go = st[bl * 132 + 96 + jj] + gxrow[768];
                float si = 1.f / (1.f + expf(-gi));
                float sf = 1.f / (1.f + expf(-gf));
                float so = 1.f / (1.f + expf(-go));
                float cn = sf * creg[r] + si * tanhf(gg);
                creg[r] = cn;
                hdst[(size_t)b * HH + jcol] = so * tanhf(cn);
            }
        }

        // device-wide per-direction step barrier
        __threadfence();
        __syncthreads();
        if (tid == 0) {
            atomicAdd(barp, 1u);
            unsigned int target = 64u * (unsigned int)(s + 1);
            while (*(volatile unsigned int*)barp < target) {}
            __threadfence();
        }
        __syncthreads();
    }
}

// ---------------------------------------------------------------------------
// emit[b][s][t] = b_out[t] + h_f[s] . W_out[t][0:256] + h_b[len-1-s] . W_out[t][256:512]
// ---------------------------------------------------------------------------
__global__ __launch_bounds__(256) void emit_kernel(
    const float* __restrict__ Wout, const float* __restrict__ bout,
    const int* __restrict__ lens)
{
    int b = blockIdx.x;
    int s0 = blockIdx.y * 8;
    int len = lens[b];
    if (s0 >= len) return;

    __shared__ float hbuf[8][512];
    __shared__ float Wt[32][65];

    int tid = threadIdx.x;
    for (int idx = tid; idx < 8 * 512; idx += 256) {
        int sl = idx >> 9, k = idx & 511;
        int s = s0 + sl;
        float vv = 0.f;
        if (s < len)
            vv = (k < 256) ? g_h[0][s + 1][b][k]
                           : g_h[1][len - s][b][k - 256];
        hbuf[sl][k] = vv;
    }

    int t  = tid & 31;
    int sl = tid >> 5;
    float acc = 0.f;
    for (int kc = 0; kc < 512; kc += 64) {
        __syncthreads();
        for (int idx = tid; idx < 32 * 64; idx += 256) {
            int tt = idx >> 6, kk = idx & 63;
            Wt[tt][kk] = Wout[tt * 512 + kc + kk];
        }
        __syncthreads();
        #pragma unroll
        for (int k = 0; k < 64; k++)
            acc += hbuf[sl][kc + k] * Wt[t][k];
    }
    int s = s0 + sl;
    if (s < len)
        g_emit[b][s][t] = acc + bout[t];
}

// ---------------------------------------------------------------------------
// Per-batch CRF: one warp per batch element.
// ---------------------------------------------------------------------------
__global__ void crf_kernel(
    const float* __restrict__ trans,
    const int* __restrict__ tags,
    const int* __restrict__ lens,
    float* __restrict__ out)
{
    int b = blockIdx.x;
    int j = threadIdx.x;
    __shared__ float tr[32][33];
    __shared__ float alpha[32];

    int len = lens[b];
    for (int idx = j; idx < 1024; idx += 32)
        tr[idx >> 5][idx & 31] = trans[idx];
    __syncwarp();

    const int* tg = tags + b * SS;
    const float* em = &g_emit[b][0][0];

    float rs = 0.f;
    for (int s = j; s < len; s += 32) {
        int t1 = tg[s];
        float v = em[s * 32 + t1];
        if (s > 0) v += tr[tg[s - 1]][t1];
        rs += v;
    }
    #pragma unroll
    for (int o = 16; o; o >>= 1) rs += __shfl_xor_sync(0xffffffffu, rs, o);

    alpha[j] = em[j];
    __syncwarp();
    for (int s = 1; s < len; s++) {
        float m = -1e30f;
        #pragma unroll
        for (int i = 0; i < 32; i++) m = fmaxf(m, alpha[i] + tr[i][j]);
        float sum = 0.f;
        #pragma unroll
        for (int i = 0; i < 32; i++) sum += expf(alpha[i] + tr[i][j] - m);
        float nj = m + logf(sum) + em[s * 32 + j];
        __syncwarp();
        alpha[j] = nj;
        __syncwarp();
    }

    float a = alpha[j];
    float m = a;
    #pragma unroll
    for (int o = 16; o; o >>= 1) m = fmaxf(m, __shfl_xor_sync(0xffffffffu, m, o));
    float e = expf(a - m);
    #pragma unroll
    for (int o = 16; o; o >>= 1) e += __shfl_xor_sync(0xffffffffu, e, o);
    float logz = m + logf(e);
    if (j == 0) out[b] = logz - rs;
}

// ---------------------------------------------------------------------------
extern "C" void kernel_launch(void* const* d_in, const int* in_sizes, int n_in,
                              void* d_out, int out_size)
{
    const float* embed = (const float*)d_in[0];
    const float* Wih_f = (const float*)d_in[1];
    const float* Whh_f = (const float*)d_in[2];
    const float* bih_f = (const float*)d_in[3];
    const float* bhh_f = (const float*)d_in[4];
    const float* Wih_b = (const float*)d_in[5];
    const float* Whh_b = (const float*)d_in[6];
    const float* bih_b = (const float*)d_in[7];
    const float* bhh_b = (const float*)d_in[8];
    const float* Wout  = (const float*)d_in[9];
    const float* bout  = (const float*)d_in[10];
    const float* trans = (const float*)d_in[11];
    const int* sent = (const int*)d_in[12];
    const int* tags = (const int*)d_in[13];
    const int* lens = (const int*)d_in[14];
    float* out = (float*)d_out;

    cudaFuncSetAttribute(gemm_inproj_tc,
                         cudaFuncAttributeMaxDynamicSharedMemorySize, INP_SMEM);
    cudaFuncSetAttribute(lstm_persist,
                         cudaFuncAttributeMaxDynamicSharedMemorySize, LSTM_SMEM);

    init_kernel<<<512, 256>>>();

    dim3 g1(2048, 8, 2);
    gemm_inproj_tc<<<g1, 256, INP_SMEM>>>(embed, Wih_f, Wih_b,
                                          bih_f, bhh_f, bih_b, bhh_b, sent, lens);

    lstm_persist<<<128, 256, LSTM_SMEM>>>(Whh_f, Whh_b, lens);

    dim3 ge(256, 64);
    emit_kernel<<<ge, 256>>>(Wout, bout, lens);

    crf_kernel<<<256, 32>>>(trans, tags, lens, out);
}

// round 4
// speedup vs baseline: 1.5976x; 1.0690x over previous
#include <cuda_runtime.h>
#include <math.h>
#include <stdint.h>

#define SS 512
#define BB 256
#define EE 256
#define HH 256
#define GG 1024   // 4*H
#define TT 32

// Scratch (device globals: allocation-free contract)
__device__ float g_gx[2][SS][BB][GG];      // pre-activations (input proj + biases)
__device__ float g_h[2][SS + 1][BB][HH];   // hidden states, slot 0 = zeros
__device__ float g_emit[BB][SS][TT];       // emission scores

// ---------------------------------------------------------------------------
__device__ __forceinline__ uint32_t f2tf32(float x) {
    uint32_t u;
    asm("cvt.rna.tf32.f32 %0, %1;" : "=r"(u) : "f"(x));
    return u;
}

__device__ __forceinline__ void mma_tf32(float d[4], const uint32_t a[4], const uint32_t b[2]) {
    asm volatile(
        "mma.sync.aligned.m16n8k8.row.col.f32.tf32.tf32.f32 "
        "{%0,%1,%2,%3}, {%4,%5,%6,%7}, {%8,%9}, {%0,%1,%2,%3};\n"
        : "+f"(d[0]), "+f"(d[1]), "+f"(d[2]), "+f"(d[3])
        : "r"(a[0]), "r"(a[1]), "r"(a[2]), "r"(a[3]), "r"(b[0]), "r"(b[1]));
}

#define CLUSTER_SYNC() do { \
    asm volatile("barrier.cluster.arrive.aligned;" ::: "memory"); \
    asm volatile("barrier.cluster.wait.aligned;" ::: "memory"); \
} while (0)

// ---------------------------------------------------------------------------
// Zero per-launch mutable state: h slot 0.
// ---------------------------------------------------------------------------
__global__ void init_kernel() {
    int idx = blockIdx.x * blockDim.x + threadIdx.x;
    if (idx < 2 * BB * HH) {
        int dir = idx >> 16;
        int rem = idx & 65535;
        g_h[dir][0][rem >> 8][rem & 255] = 0.f;
    }
}

// ---------------------------------------------------------------------------
// Input projection with fused embedding gather (TF32 tensor cores):
//   gx[dir][s][b][n] = sum_e embed[row][e] * W_ih[n][e] + b_ih[n] + b_hh[n]
// Block tile: 64 (batch rows at fixed s) x 128 (gate cols), K=256 smem-resident.
// ---------------------------------------------------------------------------
#define INP_SMEM ((64 * 260 + 128 * 260) * 4)

__global__ __launch_bounds__(256) void gemm_inproj_tc(
    const float* __restrict__ embed,
    const float* __restrict__ Wf, const float* __restrict__ Wb,
    const float* __restrict__ bih_f, const float* __restrict__ bhh_f,
    const float* __restrict__ bih_b, const float* __restrict__ bhh_b,
    const int* __restrict__ sent, const int* __restrict__ lens)
{
    extern __shared__ float sm[];
    float* As = sm;             // [64][260]
    float* Ws = sm + 64 * 260;  // [128][260]
    __shared__ int rowid[64];

    const int dir = blockIdx.z;
    const int m0 = blockIdx.x * 64;
    const int n0 = blockIdx.y * 128;
    const int s  = m0 >> 8;
    const int bf = m0 & 255;
    if (s >= lens[bf]) return;   // lengths sorted desc

    const int tid = threadIdx.x;
    if (tid < 64) {
        int b = bf + tid;
        int len = lens[b];
        int ss = (dir == 1 && s < len) ? (len - 1 - s) : s;
        rowid[tid] = sent[b * SS + ss];
    }
    __syncthreads();

    for (int idx = tid; idx < 64 * 64; idx += 256) {
        int r = idx >> 6, q = (idx & 63) * 4;
        float4 v = *(const float4*)(embed + (size_t)rowid[r] * EE + q);
        float* dst = As + r * 260 + q;
        dst[0] = __uint_as_float(f2tf32(v.x));
        dst[1] = __uint_as_float(f2tf32(v.y));
        dst[2] = __uint_as_float(f2tf32(v.z));
        dst[3] = __uint_as_float(f2tf32(v.w));
    }
    const float* __restrict__ W = dir ? Wb : Wf;
    for (int idx = tid; idx < 128 * 64; idx += 256) {
        int c = idx >> 6, q = (idx & 63) * 4;
        float4 w = *(const float4*)(W + (size_t)(n0 + c) * EE + q);
        float* dst = Ws + c * 260 + q;
        dst[0] = __uint_as_float(f2tf32(w.x));
        dst[1] = __uint_as_float(f2tf32(w.y));
        dst[2] = __uint_as_float(f2tf32(w.z));
        dst[3] = __uint_as_float(f2tf32(w.w));
    }
    __syncthreads();

    const int lane = tid & 31, wid = tid >> 5;
    const int wm = wid & 3, wn = wid >> 2;
    const int lr = lane >> 2, lc = lane & 3;

    float acc[8][4];
    #pragma unroll
    for (int i = 0; i < 8; i++)
        #pragma unroll
        for (int j = 0; j < 4; j++) acc[i][j] = 0.f;

    const uint32_t* au = (const uint32_t*)As;
    const uint32_t* wu = (const uint32_t*)Ws;
    const int arow = (wm * 16 + lr) * 260;

    #pragma unroll 2
    for (int kc = 0; kc < 256; kc += 8) {
        uint32_t a[4];
        a[0] = au[arow + kc + lc];
        a[1] = au[arow + 8 * 260 + kc + lc];
        a[2] = au[arow + kc + lc + 4];
        a[3] = au[arow + 8 * 260 + kc + lc + 4];
        #pragma unroll
        for (int nf = 0; nf < 8; nf++) {
            int cc = wn * 64 + nf * 8 + lr;
            uint32_t b[2];
            b[0] = wu[cc * 260 + kc + lc];
            b[1] = wu[cc * 260 + kc + lc + 4];
            mma_tf32(acc[nf], a, b);
        }
    }

    const float* bi = dir ? bih_b : bih_f;
    const float* bh = dir ? bhh_b : bhh_f;
    float* gxp = &g_gx[dir][0][0][0];
    const int row = m0 + wm * 16 + lr;
    #pragma unroll
    for (int nf = 0; nf < 8; nf++) {
        int n = n0 + wn * 64 + nf * 8 + lc * 2;
        float b0v = bi[n] + bh[n];
        float b1v = bi[n + 1] + bh[n + 1];
        *(float2*)(gxp + (size_t)row * GG + n) =
            make_float2(acc[nf][0] + b0v, acc[nf][1] + b1v);
        *(float2*)(gxp + (size_t)(row + 8) * GG + n) =
            make_float2(acc[nf][2] + b0v, acc[nf][3] + b1v);
    }
}

// ---------------------------------------------------------------------------
// Persistent bidirectional LSTM, cluster version.
// Grid (8, 16): x = j-tile (cluster member), y = dir*8 + batch-tile.
// Each cluster = the 8 j-tile CTAs of one (dir, batch-tile); h is exchanged
// through gmem/L2 with barrier.cluster (HW, ~400cyc) per step. W_hh tile
// stays in smem for the whole sequence; cell state in registers.
// ---------------------------------------------------------------------------
#define LSTM_SMEM ((128 * 260 + 32 * 260 + 32 * 132) * 4)

__global__ __launch_bounds__(256, 1) __cluster_dims__(8, 1, 1)
void lstm_persist(
    const float* __restrict__ Whh_f, const float* __restrict__ Whh_b,
    const int* __restrict__ lens)
{
    extern __shared__ float sm[];
    float* Ws = sm;                       // [128][260] tf32 weights
    float* hs = sm + 128 * 260;           // [32][260] tf32 h_prev tile
    float* st = hs + 32 * 260;            // [32][132] gate staging

    const int tid = threadIdx.x;
    const int dir = blockIdx.y >> 3;
    const int mb  = blockIdx.y & 7;       // batch tile
    const int jt  = blockIdx.x;           // hidden-unit tile = cluster rank
    const int b0 = mb * 32;
    const int lenmax = lens[b0];          // same for all CTAs in cluster

    // Load weights once (tf32). Block col c -> gate g = c>>5, j = jt*32 + (c&31)
    const float* __restrict__ W = dir ? Whh_b : Whh_f;
    for (int idx = tid; idx < 128 * 64; idx += 256) {
        int c = idx >> 6, q = (idx & 63) * 4;
        int n = ((c >> 5) << 8) + jt * 32 + (c & 31);
        float4 w = *(const float4*)(W + (size_t)n * HH + q);
        float* dst = Ws + c * 260 + q;
        dst[0] = __uint_as_float(f2tf32(w.x));
        dst[1] = __uint_as_float(f2tf32(w.y));
        dst[2] = __uint_as_float(f2tf32(w.z));
        dst[3] = __uint_as_float(f2tf32(w.w));
    }

    const int lane = tid & 31, wid = tid >> 5;
    const int wm = wid >> 2;      // 0..1 : 16-row batch slab
    const int wn = wid & 3;       // 0..3 : gate
    const int lr = lane >> 2, lc = lane & 3;

    float creg[4] = {0.f, 0.f, 0.f, 0.f};

    const float* gxbase = &g_gx[dir][0][0][0];
    float* hbase = &g_h[dir][0][0][0];

    const uint32_t* hsu = (const uint32_t*)hs;
    const uint32_t* wsu = (const uint32_t*)Ws;
    const int arow = (wm * 16 + lr) * 260;

    for (int s = 0; s < lenmax; s++) {
        // load h_prev tile as tf32 (written by all 8 cluster CTAs last step)
        const float* hsrc = hbase + (size_t)s * BB * HH + (size_t)b0 * HH;
        for (int idx = tid; idx < 32 * 64; idx += 256) {
            int r = idx >> 6, q = (idx & 63) * 4;
            float4 v = *(const float4*)(hsrc + r * HH + q);
            float* dst = hs + r * 260 + q;
            dst[0] = __uint_as_float(f2tf32(v.x));
            dst[1] = __uint_as_float(f2tf32(v.y));
            dst[2] = __uint_as_float(f2tf32(v.z));
            dst[3] = __uint_as_float(f2tf32(v.w));
        }
        __syncthreads();

        float acc[4][4];
        #pragma unroll
        for (int i = 0; i < 4; i++)
            #pragma unroll
            for (int j = 0; j < 4; j++) acc[i][j] = 0.f;

        #pragma unroll 4
        for (int kc = 0; kc < 256; kc += 8) {
            uint32_t a[4];
            a[0] = hsu[arow + kc + lc];
            a[1] = hsu[arow + 8 * 260 + kc + lc];
            a[2] = hsu[arow + kc + lc + 4];
            a[3] = hsu[arow + 8 * 260 + kc + lc + 4];
            #pragma unroll
            for (int nf = 0; nf < 4; nf++) {
                int cc = wn * 32 + nf * 8 + lr;
                uint32_t b[2];
                b[0] = wsu[cc * 260 + kc + lc];
                b[1] = wsu[cc * 260 + kc + lc + 4];
                mma_tf32(acc[nf], a, b);
            }
        }

        // stage gemm result (block cols: c = gate*32 + j_local)
        {
            int r = wm * 16 + lr;
            #pragma unroll
            for (int nf = 0; nf < 4; nf++) {
                int c = wn * 32 + nf * 8 + lc * 2;
                *(float2*)(st + r * 132 + c) = make_float2(acc[nf][0], acc[nf][1]);
                *(float2*)(st + (r + 8) * 132 + c) = make_float2(acc[nf][2], acc[nf][3]);
            }
        }
        __syncthreads();

        // gate epilogue: 1024 (b,j) pairs, 4 per thread
        const float* gxs = gxbase + (size_t)s * BB * GG;
        float* hdst = hbase + (size_t)(s + 1) * BB * HH;
        #pragma unroll
        for (int r = 0; r < 4; r++) {
            int p = r * 256 + tid;
            int bl = p >> 5, jj = p & 31;
            int b = b0 + bl;
            int jcol = jt * 32 + jj;
            const float* gxrow = gxs + (size_t)b * GG + jcol;
            float gi = st[bl * 132 + jj]      + gxrow[0];
            float gf = st[bl * 132 + 32 + jj] + gxrow[256];
            float gg = st[bl * 132 + 64 + jj] + gxrow[512];
            float go = st[bl * 132 + 96 + jj] + gxrow[768];
            float si = 1.f / (1.f + __expf(-gi));
            float sf = 1.f / (1.f + __expf(-gf));
            float so = 1.f / (1.f + __expf(-go));
            float cn = sf * creg[r] + si * tanhf(gg);
            creg[r] = cn;
            hdst[(size_t)b * HH + jcol] = so * tanhf(cn);
        }

        // HW cluster barrier: release our h writes, acquire peers'.
        CLUSTER_SYNC();
    }
}

// ---------------------------------------------------------------------------
// emit[b][s][t] = b_out[t] + h_f[s] . W_out[t][0:256] + h_b[len-1-s] . W_out[t][256:512]
// Block: one b, 16 s-values (warp w -> rows w and w+8), 32 tags. Vectorized LDS.
// ---------------------------------------------------------------------------
__global__ __launch_bounds__(256) void emit_kernel(
    const float* __restrict__ Wout, const float* __restrict__ bout,
    const int* __restrict__ lens)
{
    int b = blockIdx.x;
    int s0 = blockIdx.y * 16;
    int len = lens[b];
    if (s0 >= len) return;

    __shared__ float hbuf[16][512];
    __shared__ float Wt[32][68];

    int tid = threadIdx.x;
    for (int idx = tid; idx < 16 * 128; idx += 256) {
        int sl = idx >> 7;
        int q = (idx & 127) * 4;
        int s = s0 + sl;
        float4 v = make_float4(0.f, 0.f, 0.f, 0.f);
        if (s < len) {
            if (q < 256) v = *(const float4*)&g_h[0][s + 1][b][q];
            else         v = *(const float4*)&g_h[1][len - s][b][q - 256];
        }
        *(float4*)&hbuf[sl][q] = v;
    }

    int t = tid & 31;
    int w = tid >> 5;    // warp index: handles s rows w and w+8
    float acc0 = 0.f, acc1 = 0.f;
    for (int kc = 0; kc < 512; kc += 64) {
        __syncthreads();
        for (int idx = tid; idx < 32 * 16; idx += 256) {
            int tt = idx >> 4, q = (idx & 15) * 4;
            *(float4*)&Wt[tt][q] = *(const float4*)&Wout[tt * 512 + kc + q];
        }
        __syncthreads();
        #pragma unroll
        for (int k = 0; k < 64; k += 4) {
            float4 wv = *(const float4*)&Wt[t][k];
            float4 h0 = *(const float4*)&hbuf[w][kc + k];
            float4 h1 = *(const float4*)&hbuf[w + 8][kc + k];
            acc0 += h0.x * wv.x + h0.y * wv.y + h0.z * wv.z + h0.w * wv.w;
            acc1 += h1.x * wv.x + h1.y * wv.y + h1.z * wv.z + h1.w * wv.w;
        }
    }
    if (s0 + w < len)     g_emit[b][s0 + w][t]     = acc0 + bout[t];
    if (s0 + w + 8 < len) g_emit[b][s0 + w + 8][t] = acc1 + bout[t];
}

// ---------------------------------------------------------------------------
// Per-batch CRF: one warp per batch element.
// ---------------------------------------------------------------------------
__global__ void crf_kernel(
    const float* __restrict__ trans,
    const int* __restrict__ tags,
    const int* __restrict__ lens,
    float* __restrict__ out)
{
    int b = blockIdx.x;
    int j = threadIdx.x;
    __shared__ float tr[32][33];
    __shared__ float alpha[32];

    int len = lens[b];
    for (int idx = j; idx < 1024; idx += 32)
        tr[idx >> 5][idx & 31] = trans[idx];
    __syncwarp();

    const int* tg = tags + b * SS;
    const float* em = &g_emit[b][0][0];

    float rs = 0.f;
    for (int s = j; s < len; s += 32) {
        int t1 = tg[s];
        float v = em[s * 32 + t1];
        if (s > 0) v += tr[tg[s - 1]][t1];
        rs += v;
    }
    #pragma unroll
    for (int o = 16; o; o >>= 1) rs += __shfl_xor_sync(0xffffffffu, rs, o);

    alpha[j] = em[j];
    __syncwarp();
    for (int s = 1; s < len; s++) {
        float m = -1e30f;
        #pragma unroll
        for (int i = 0; i < 32; i++) m = fmaxf(m, alpha[i] + tr[i][j]);
        float sum = 0.f;
        #pragma unroll
        for (int i = 0; i < 32; i++) sum += __expf(alpha[i] + tr[i][j] - m);
        float nj = m + __logf(sum) + em[s * 32 + j];
        __syncwarp();
        alpha[j] = nj;
        __syncwarp();
    }

    float a = alpha[j];
    float m = a;
    #pragma unroll
    for (int o = 16; o; o >>= 1) m = fmaxf(m, __shfl_xor_sync(0xffffffffu, m, o));
    float e = __expf(a - m);
    #pragma unroll
    for (int o = 16; o; o >>= 1) e += __shfl_xor_sync(0xffffffffu, e, o);
    float logz = m + __logf(e);
    if (j == 0) out[b] = logz - rs;
}

// ---------------------------------------------------------------------------
extern "C" void kernel_launch(void* const* d_in, const int* in_sizes, int n_in,
                              void* d_out, int out_size)
{
    const float* embed = (const float*)d_in[0];
    const float* Wih_f = (const float*)d_in[1];
    const float* Whh_f = (const float*)d_in[2];
    const float* bih_f = (const float*)d_in[3];
    const float* bhh_f = (const float*)d_in[4];
    const float* Wih_b = (const float*)d_in[5];
    const float* Whh_b = (const float*)d_in[6];
    const float* bih_b = (const float*)d_in[7];
    const float* bhh_b = (const float*)d_in[8];
    const float* Wout  = (const float*)d_in[9];
    const float* bout  = (const float*)d_in[10];
    const float* trans = (const float*)d_in[11];
    const int* sent = (const int*)d_in[12];
    const int* tags = (const int*)d_in[13];
    const int* lens = (const int*)d_in[14];
    float* out = (float*)d_out;

    cudaFuncSetAttribute(gemm_inproj_tc,
                         cudaFuncAttributeMaxDynamicSharedMemorySize, INP_SMEM);
    cudaFuncSetAttribute(lstm_persist,
                         cudaFuncAttributeMaxDynamicSharedMemorySize, LSTM_SMEM);

    init_kernel<<<512, 256>>>();

    dim3 g1(2048, 8, 2);
    gemm_inproj_tc<<<g1, 256, INP_SMEM>>>(embed, Wih_f, Wih_b,
                                          bih_f, bhh_f, bih_b, bhh_b, sent, lens);

    dim3 gl(8, 16);
    lstm_persist<<<gl, 256, LSTM_SMEM>>>(Whh_f, Whh_b, lens);

    dim3 ge(256, 32);
    emit_kernel<<<ge, 256>>>(Wout, bout, lens);

    crf_kernel<<<256, 32>>>(trans, tags, lens, out);
}

// round 5
// speedup vs baseline: 1.9359x; 1.2118x over previous
#include <cuda_runtime.h>
#include <cuda_bf16.h>
#include <math.h>
#include <stdint.h>

#define SS 512
#define BB 256
#define EE 256
#define HH 256
#define GG 1024   // 4*H
#define TT 32

// Scratch (device globals: allocation-free contract)
__device__ float g_gx[2][SS][BB][GG];      // pre-activations (input proj + biases)
__device__ float g_h[2][SS + 1][BB][HH];   // hidden states (slot 0 unused)
__device__ float g_emit[BB][SS][TT];       // emission scores

// ---------------------------------------------------------------------------
__device__ __forceinline__ void mma_bf16(float d[4], const uint32_t a[4], const uint32_t b[2]) {
    asm volatile(
        "mma.sync.aligned.m16n8k16.row.col.f32.bf16.bf16.f32 "
        "{%0,%1,%2,%3}, {%4,%5,%6,%7}, {%8,%9}, {%0,%1,%2,%3};\n"
        : "+f"(d[0]), "+f"(d[1]), "+f"(d[2]), "+f"(d[3])
        : "r"(a[0]), "r"(a[1]), "r"(a[2]), "r"(a[3]), "r"(b[0]), "r"(b[1]));
}

__device__ __forceinline__ uint32_t pack_bf16(float lo, float hi) {
    __nv_bfloat162 t = __floats2bfloat162_rn(lo, hi);  // x=lo, y=hi
    return *(uint32_t*)&t;
}

__device__ __forceinline__ uint32_t smem_u32(const void* p) {
    uint32_t a;
    asm("{ .reg .u64 t; cvta.to.shared.u64 t, %1; cvt.u32.u64 %0, t; }"
        : "=r"(a) : "l"(p));
    return a;
}

#define CLUSTER_SYNC() do { \
    asm volatile("barrier.cluster.arrive.aligned;" ::: "memory"); \
    asm volatile("barrier.cluster.wait.aligned;" ::: "memory"); \
} while (0)

// ---------------------------------------------------------------------------
// Input projection with fused embedding gather (bf16 tensor cores):
//   gx[dir][s][b][n] = sum_e embed[row][e] * W_ih[n][e] + b_ih[n] + b_hh[n]
// Block tile: 64 (batch rows at fixed s) x 128 (gate cols), K=256 smem-resident
// in bf16 (101 KB -> 2 CTAs/SM). Warp tile 16x64, m16n8k16.
// ---------------------------------------------------------------------------
#define INP_SMEM ((64 + 128) * 132 * 4)

__global__ __launch_bounds__(256) void gemm_inproj_tc(
    const float* __restrict__ embed,
    const float* __restrict__ Wf, const float* __restrict__ Wb,
    const float* __restrict__ bih_f, const float* __restrict__ bhh_f,
    const float* __restrict__ bih_b, const float* __restrict__ bhh_b,
    const int* __restrict__ sent, const int* __restrict__ lens)
{
    extern __shared__ uint32_t smw[];
    uint32_t* au = smw;              // A: 64 rows x 132 words (bf16x2)
    uint32_t* wu = smw + 64 * 132;   // W: 128 rows x 132 words
    __shared__ int rowid[64];

    const int dir = blockIdx.z;
    const int m0 = blockIdx.x * 64;
    const int n0 = blockIdx.y * 128;
    const int s  = m0 >> 8;
    const int bf = m0 & 255;
    if (s >= lens[bf]) return;   // lengths sorted desc

    const int tid = threadIdx.x;
    if (tid < 64) {
        int b = bf + tid;
        int len = lens[b];
        int ss = (dir == 1 && s < len) ? (len - 1 - s) : s;
        rowid[tid] = sent[b * SS + ss];
    }
    __syncthreads();

    for (int idx = tid; idx < 64 * 64; idx += 256) {
        int r = idx >> 6, q4 = idx & 63;
        float4 v = *(const float4*)(embed + (size_t)rowid[r] * EE + q4 * 4);
        au[r * 132 + q4 * 2]     = pack_bf16(v.x, v.y);
        au[r * 132 + q4 * 2 + 1] = pack_bf16(v.z, v.w);
    }
    const float* __restrict__ W = dir ? Wb : Wf;
    for (int idx = tid; idx < 128 * 64; idx += 256) {
        int c = idx >> 6, q4 = idx & 63;
        float4 w = *(const float4*)(W + (size_t)(n0 + c) * EE + q4 * 4);
        wu[c * 132 + q4 * 2]     = pack_bf16(w.x, w.y);
        wu[c * 132 + q4 * 2 + 1] = pack_bf16(w.z, w.w);
    }
    __syncthreads();

    const int lane = tid & 31, wid = tid >> 5;
    const int wm = wid & 3, wn = wid >> 2;
    const int lr = lane >> 2, lc = lane & 3;

    float acc[8][4];
    #pragma unroll
    for (int i = 0; i < 8; i++)
        #pragma unroll
        for (int j = 0; j < 4; j++) acc[i][j] = 0.f;

    const int arow = (wm * 16 + lr) * 132;

    #pragma unroll 4
    for (int kc = 0; kc < 128; kc += 8) {   // word index; 8 words = 16 k
        uint32_t a[4];
        a[0] = au[arow + kc + lc];
        a[1] = au[arow + 8 * 132 + kc + lc];
        a[2] = au[arow + kc + 4 + lc];
        a[3] = au[arow + 8 * 132 + kc + 4 + lc];
        #pragma unroll
        for (int nf = 0; nf < 8; nf++) {
            int cc = wn * 64 + nf * 8 + lr;
            uint32_t b[2];
            b[0] = wu[cc * 132 + kc + lc];
            b[1] = wu[cc * 132 + kc + 4 + lc];
            mma_bf16(acc[nf], a, b);
        }
    }

    const float* bi = dir ? bih_b : bih_f;
    const float* bh = dir ? bhh_b : bhh_f;
    float* gxp = &g_gx[dir][0][0][0];
    const int row = m0 + wm * 16 + lr;
    #pragma unroll
    for (int nf = 0; nf < 8; nf++) {
        int n = n0 + wn * 64 + nf * 8 + lc * 2;
        float b0v = bi[n] + bh[n];
        float b1v = bi[n + 1] + bh[n + 1];
        *(float2*)(gxp + (size_t)row * GG + n) =
            make_float2(acc[nf][0] + b0v, acc[nf][1] + b1v);
        *(float2*)(gxp + (size_t)(row + 8) * GG + n) =
            make_float2(acc[nf][2] + b0v, acc[nf][3] + b1v);
    }
}

// ---------------------------------------------------------------------------
// Persistent bidirectional LSTM: clusters of 4 CTAs, one cluster per
// (dir, 32-batch tile). Each CTA owns 256 gate cols (4 gates x 64 j), bf16
// W_hh tile (132 KB) resident in smem for all steps. Per step, each CTA
// computes a 32x256x256 bf16 MMA, applies gates for its 64 j-cols, and
// broadcasts its bf16 h-slice into all 4 cluster CTAs' smem via DSMEM
// (double-buffered). One cluster.sync per step (release/acquire).
// ---------------------------------------------------------------------------
#define LSTM_ST_WORDS (32 * 260)           // fp32 staging
#define LSTM_WS_WORDS (256 * 132)          // bf16x2 weights
#define LSTM_HS_WORDS (2 * 32 * 132)       // bf16x2 h, double-buffered
#define LSTM_SMEM ((LSTM_ST_WORDS + LSTM_WS_WORDS + LSTM_HS_WORDS) * 4)

__global__ __launch_bounds__(256, 1) __cluster_dims__(4, 1, 1)
void lstm_persist(
    const float* __restrict__ Whh_f, const float* __restrict__ Whh_b,
    const int* __restrict__ lens)
{
    extern __shared__ float smf[];
    float* st = smf;                                    // [32][260] fp32
    uint32_t* wsu = (uint32_t*)(smf + LSTM_ST_WORDS);   // [256][132] bf16x2
    uint32_t* hsu = wsu + LSTM_WS_WORDS;                // [2][32][132] bf16x2

    const int tid = threadIdx.x;
    const int jt  = blockIdx.x;          // cluster rank, 0..3
    const int dir = blockIdx.y >> 3;
    const int mb  = blockIdx.y & 7;
    const int b0  = mb * 32;
    const int lenmax = lens[b0];         // same for whole cluster

    // Load bf16 weights once. Local col c (0..255) -> gate g=c>>6, j=jt*64+(c&63)
    const float* __restrict__ W = dir ? Whh_b : Whh_f;
    for (int idx = tid; idx < 256 * 64; idx += 256) {
        int c = idx >> 6, q4 = idx & 63;
        int n = ((c >> 6) << 8) + jt * 64 + (c & 63);
        float4 w = *(const float4*)(W + (size_t)n * HH + q4 * 4);
        wsu[c * 132 + q4 * 2]     = pack_bf16(w.x, w.y);
        wsu[c * 132 + q4 * 2 + 1] = pack_bf16(w.z, w.w);
    }
    for (int idx = tid; idx < LSTM_HS_WORDS; idx += 256) hsu[idx] = 0u;

    const int lane = tid & 31, w = tid >> 5;
    const int lr = lane >> 2, lc = lane & 3;
    const int bl = tid >> 3;             // epilogue batch row 0..31
    const int j8 = (tid & 7) * 8;        // epilogue j group

    float creg[8] = {0.f,0.f,0.f,0.f,0.f,0.f,0.f,0.f};

    const float* gxbase = &g_gx[dir][0][0][0];
    float* hbase = &g_h[dir][0][0][0];
    const uint32_t hs_base = smem_u32(hsu);

    // peers must finish zero-init before anyone's step-0 remote writes land
    CLUSTER_SYNC();

    for (int s = 0; s < lenmax; s++) {
        const uint32_t* hb = hsu + (s & 1) * (32 * 132);

        float acc[2][4][4];
        #pragma unroll
        for (int mf = 0; mf < 2; mf++)
            #pragma unroll
            for (int nf = 0; nf < 4; nf++)
                #pragma unroll
                for (int q = 0; q < 4; q++) acc[mf][nf][q] = 0.f;

        #pragma unroll 4
        for (int kc = 0; kc < 128; kc += 8) {   // 8 words = 16 k
            uint32_t a0[4], a1[4];
            a0[0] = hb[lr * 132 + kc + lc];
            a0[1] = hb[(lr + 8) * 132 + kc + lc];
            a0[2] = hb[lr * 132 + kc + 4 + lc];
            a0[3] = hb[(lr + 8) * 132 + kc + 4 + lc];
            a1[0] = hb[(16 + lr) * 132 + kc + lc];
            a1[1] = hb[(24 + lr) * 132 + kc + lc];
            a1[2] = hb[(16 + lr) * 132 + kc + 4 + lc];
            a1[3] = hb[(24 + lr) * 132 + kc + 4 + lc];
            #pragma unroll
            for (int nf = 0; nf < 4; nf++) {
                int cc = w * 32 + nf * 8 + lr;
                uint32_t b[2];
                b[0] = wsu[cc * 132 + kc + lc];
                b[1] = wsu[cc * 132 + kc + 4 + lc];
                mma_bf16(acc[0][nf], a0, b);
                mma_bf16(acc[1][nf], a1, b);
            }
        }

        // stage GEMM result: st[batch 0..31][local col 0..255]
        #pragma unroll
        for (int mf = 0; mf < 2; mf++)
            #pragma unroll
            for (int nf = 0; nf < 4; nf++) {
                int row = mf * 16 + lr, col = w * 32 + nf * 8 + lc * 2;
                *(float2*)&st[row * 260 + col] =
                    make_float2(acc[mf][nf][0], acc[mf][nf][1]);
                *(float2*)&st[(row + 8) * 260 + col] =
                    make_float2(acc[mf][nf][2], acc[mf][nf][3]);
            }
        __syncthreads();

        // epilogue: thread handles batch bl, j cols j8..j8+7
        const float* gxr = gxbase + (size_t)s * BB * GG
                         + (size_t)(b0 + bl) * GG + jt * 64 + j8;
        float gi[8], gf[8], gg[8], go[8];
        {
            float4 v0, v1, x0, x1;
            v0 = *(const float4*)&st[bl * 260 + j8];
            v1 = *(const float4*)&st[bl * 260 + j8 + 4];
            x0 = *(const float4*)(gxr);
            x1 = *(const float4*)(gxr + 4);
            gi[0]=v0.x+x0.x; gi[1]=v0.y+x0.y; gi[2]=v0.z+x0.z; gi[3]=v0.w+x0.w;
            gi[4]=v1.x+x1.x; gi[5]=v1.y+x1.y; gi[6]=v1.z+x1.z; gi[7]=v1.w+x1.w;
            v0 = *(const float4*)&st[bl * 260 + 64 + j8];
            v1 = *(const float4*)&st[bl * 260 + 64 + j8 + 4];
            x0 = *(const float4*)(gxr + 256);
            x1 = *(const float4*)(gxr + 260);
            gf[0]=v0.x+x0.x; gf[1]=v0.y+x0.y; gf[2]=v0.z+x0.z; gf[3]=v0.w+x0.w;
            gf[4]=v1.x+x1.x; gf[5]=v1.y+x1.y; gf[6]=v1.z+x1.z; gf[7]=v1.w+x1.w;
            v0 = *(const float4*)&st[bl * 260 + 128 + j8];
            v1 = *(const float4*)&st[bl * 260 + 128 + j8 + 4];
            x0 = *(const float4*)(gxr + 512);
            x1 = *(const float4*)(gxr + 516);
            gg[0]=v0.x+x0.x; gg[1]=v0.y+x0.y; gg[2]=v0.z+x0.z; gg[3]=v0.w+x0.w;
            gg[4]=v1.x+x1.x; gg[5]=v1.y+x1.y; gg[6]=v1.z+x1.z; gg[7]=v1.w+x1.w;
            v0 = *(const float4*)&st[bl * 260 + 192 + j8];
            v1 = *(const float4*)&st[bl * 260 + 192 + j8 + 4];
            x0 = *(const float4*)(gxr + 768);
            x1 = *(const float4*)(gxr + 772);
            go[0]=v0.x+x0.x; go[1]=v0.y+x0.y; go[2]=v0.z+x0.z; go[3]=v0.w+x0.w;
            go[4]=v1.x+x1.x; go[5]=v1.y+x1.y; go[6]=v1.z+x1.z; go[7]=v1.w+x1.w;
        }

        float hn[8];
        #pragma unroll
        for (int k = 0; k < 8; k++) {
            float si = 1.f / (1.f + __expf(-gi[k]));
            float sf = 1.f / (1.f + __expf(-gf[k]));
            float so = 1.f / (1.f + __expf(-go[k]));
            float cn = sf * creg[k] + si * tanhf(gg[k]);
            creg[k] = cn;
            hn[k] = so * tanhf(cn);
        }

        // fp32 h to gmem for emit
        float* hd = hbase + (size_t)(s + 1) * BB * HH
                  + (size_t)(b0 + bl) * HH + jt * 64 + j8;
        *(float4*)hd       = make_float4(hn[0], hn[1], hn[2], hn[3]);
        *(float4*)(hd + 4) = make_float4(hn[4], hn[5], hn[6], hn[7]);

        // bf16 h broadcast into all 4 cluster CTAs' next-step buffer
        uint32_t pw0 = pack_bf16(hn[0], hn[1]);
        uint32_t pw1 = pack_bf16(hn[2], hn[3]);
        uint32_t pw2 = pack_bf16(hn[4], hn[5]);
        uint32_t pw3 = pack_bf16(hn[6], hn[7]);
        uint32_t woff = (uint32_t)(((s + 1) & 1) * (32 * 132)
                      + bl * 132 + ((jt * 64 + j8) >> 1));
        uint32_t baddr = hs_base + woff * 4;
        #pragma unroll
        for (int r = 0; r < 4; r++) {
            uint32_t ra;
            asm("mapa.shared::cluster.u32 %0, %1, %2;" : "=r"(ra) : "r"(baddr), "r"(r));
            asm volatile("st.shared::cluster.b32 [%0], %1;" :: "r"(ra), "r"(pw0) : "memory");
            asm volatile("st.shared::cluster.b32 [%0], %1;" :: "r"(ra + 4), "r"(pw1) : "memory");
            asm volatile("st.shared::cluster.b32 [%0], %1;" :: "r"(ra + 8), "r"(pw2) : "memory");
            asm volatile("st.shared::cluster.b32 [%0], %1;" :: "r"(ra + 12), "r"(pw3) : "memory");
        }

        // release our writes / acquire peers' (also acts as block barrier)
        CLUSTER_SYNC();
    }
}

// ---------------------------------------------------------------------------
// emit[b][s][t] = b_out[t] + h_f[s] . W_out[t][0:256] + h_b[len-1-s] . W_out[t][256:512]
// ---------------------------------------------------------------------------
__global__ __launch_bounds__(256) void emit_kernel(
    const float* __restrict__ Wout, const float* __restrict__ bout,
    const int* __restrict__ lens)
{
    int b = blockIdx.x;
    int s0 = blockIdx.y * 16;
    int len = lens[b];
    if (s0 >= len) return;

    __shared__ float hbuf[16][512];
    __shared__ float Wt[32][68];

    int tid = threadIdx.x;
    for (int idx = tid; idx < 16 * 128; idx += 256) {
        int sl = idx >> 7;
        int q = (idx & 127) * 4;
        int s = s0 + sl;
        float4 v = make_float4(0.f, 0.f, 0.f, 0.f);
        if (s < len) {
            if (q < 256) v = *(const float4*)&g_h[0][s + 1][b][q];
            else         v = *(const float4*)&g_h[1][len - s][b][q - 256];
        }
        *(float4*)&hbuf[sl][q] = v;
    }

    int t = tid & 31;
    int w = tid >> 5;
    float acc0 = 0.f, acc1 = 0.f;
    for (int kc = 0; kc < 512; kc += 64) {
        __syncthreads();
        for (int idx = tid; idx < 32 * 16; idx += 256) {
            int tt = idx >> 4, q = (idx & 15) * 4;
            *(float4*)&Wt[tt][q] = *(const float4*)&Wout[tt * 512 + kc + q];
        }
        __syncthreads();
        #pragma unroll
        for (int k = 0; k < 64; k += 4) {
            float4 wv = *(const float4*)&Wt[t][k];
            float4 h0 = *(const float4*)&hbuf[w][kc + k];
            float4 h1 = *(const float4*)&hbuf[w + 8][kc + k];
            acc0 += h0.x * wv.x + h0.y * wv.y + h0.z * wv.z + h0.w * wv.w;
            acc1 += h1.x * wv.x + h1.y * wv.y + h1.z * wv.z + h1.w * wv.w;
        }
    }
    if (s0 + w < len)     g_emit[b][s0 + w][t]     = acc0 + bout[t];
    if (s0 + w + 8 < len) g_emit[b][s0 + w + 8][t] = acc1 + bout[t];
}

// ---------------------------------------------------------------------------
// Per-batch CRF: one warp per batch element.
// ---------------------------------------------------------------------------
__global__ void crf_kernel(
    const float* __restrict__ trans,
    const int* __restrict__ tags,
    const int* __restrict__ lens,
    float* __restrict__ out)
{
    int b = blockIdx.x;
    int j = threadIdx.x;
    __shared__ float tr[32][33];
    __shared__ float alpha[32];

    int len = lens[b];
    for (int idx = j; idx < 1024; idx += 32)
        tr[idx >> 5][idx & 31] = trans[idx];
    __syncwarp();

    const int* tg = tags + b * SS;
    const float* em = &g_emit[b][0][0];

    float rs = 0.f;
    for (int s = j; s < len; s += 32) {
        int t1 = tg[s];
        float v = em[s * 32 + t1];
        if (s > 0) v += tr[tg[s - 1]][t1];
        rs += v;
    }
    #pragma unroll
    for (int o = 16; o; o >>= 1) rs += __shfl_xor_sync(0xffffffffu, rs, o);

    alpha[j] = em[j];
    __syncwarp();
    for (int s = 1; s < len; s++) {
        float m = -1e30f;
        #pragma unroll
        for (int i = 0; i < 32; i++) m = fmaxf(m, alpha[i] + tr[i][j]);
        float sum = 0.f;
        #pragma unroll
        for (int i = 0; i < 32; i++) sum += __expf(alpha[i] + tr[i][j] - m);
        float nj = m + __logf(sum) + em[s * 32 + j];
        __syncwarp();
        alpha[j] = nj;
        __syncwarp();
    }

    float a = alpha[j];
    float m = a;
    #pragma unroll
    for (int o = 16; o; o >>= 1) m = fmaxf(m, __shfl_xor_sync(0xffffffffu, m, o));
    float e = __expf(a - m);
    #pragma unroll
    for (int o = 16; o; o >>= 1) e += __shfl_xor_sync(0xffffffffu, e, o);
    float logz = m + __logf(e);
    if (j == 0) out[b] = logz - rs;
}

// ---------------------------------------------------------------------------
extern "C" void kernel_launch(void* const* d_in, const int* in_sizes, int n_in,
                              void* d_out, int out_size)
{
    const float* embed = (const float*)d_in[0];
    const float* Wih_f = (const float*)d_in[1];
    const float* Whh_f = (const float*)d_in[2];
    const float* bih_f = (const float*)d_in[3];
    const float* bhh_f = (const float*)d_in[4];
    const float* Wih_b = (const float*)d_in[5];
    const float* Whh_b = (const float*)d_in[6];
    const float* bih_b = (const float*)d_in[7];
    const float* bhh_b = (const float*)d_in[8];
    const float* Wout  = (const float*)d_in[9];
    const float* bout  = (const float*)d_in[10];
    const float* trans = (const float*)d_in[11];
    const int* sent = (const int*)d_in[12];
    const int* tags = (const int*)d_in[13];
    const int* lens = (const int*)d_in[14];
    float* out = (float*)d_out;

    cudaFuncSetAttribute(gemm_inproj_tc,
                         cudaFuncAttributeMaxDynamicSharedMemorySize, INP_SMEM);
    cudaFuncSetAttribute(lstm_persist,
                         cudaFuncAttributeMaxDynamicSharedMemorySize, LSTM_SMEM);

    dim3 g1(2048, 8, 2);
    gemm_inproj_tc<<<g1, 256, INP_SMEM>>>(embed, Wih_f, Wih_b,
                                          bih_f, bhh_f, bih_b, bhh_b, sent, lens);

    dim3 gl(4, 16);
    lstm_persist<<<gl, 256, LSTM_SMEM>>>(Whh_f, Whh_b, lens);

    dim3 ge(256, 32);
    emit_kernel<<<ge, 256>>>(Wout, bout, lens);

    crf_kernel<<<256, 32>>>(trans, tags, lens, out);
}

// round 6
// speedup vs baseline: 3.1649x; 1.6348x over previous
#include <cuda_runtime.h>
#include <cuda_bf16.h>
#include <math.h>
#include <stdint.h>

#define SS 512
#define BB 256
#define EE 256
#define HH 256
#define GG 1024   // 4*H
#define TT 32

// Scratch (device globals: allocation-free contract)
__device__ float g_gx[2][SS][BB][GG];      // pre-activations (input proj + biases)
__device__ float g_h[2][SS + 1][BB][HH];   // hidden states (slot 0 unused)
__device__ float g_emit[BB][SS][TT];       // emission scores

// ---------------------------------------------------------------------------
__device__ __forceinline__ void mma_bf16(float d[4], const uint32_t a[4], const uint32_t b[2]) {
    asm volatile(
        "mma.sync.aligned.m16n8k16.row.col.f32.bf16.bf16.f32 "
        "{%0,%1,%2,%3}, {%4,%5,%6,%7}, {%8,%9}, {%0,%1,%2,%3};\n"
        : "+f"(d[0]), "+f"(d[1]), "+f"(d[2]), "+f"(d[3])
        : "r"(a[0]), "r"(a[1]), "r"(a[2]), "r"(a[3]), "r"(b[0]), "r"(b[1]));
}

__device__ __forceinline__ uint32_t pack_bf16(float lo, float hi) {
    __nv_bfloat162 t = __floats2bfloat162_rn(lo, hi);  // x=lo, y=hi
    return *(uint32_t*)&t;
}

__device__ __forceinline__ uint32_t smem_u32(const void* p) {
    uint32_t a;
    asm("{ .reg .u64 t; cvta.to.shared.u64 t, %1; cvt.u32.u64 %0, t; }"
        : "=r"(a) : "l"(p));
    return a;
}

#define CLUSTER_SYNC() do { \
    asm volatile("barrier.cluster.arrive.aligned;" ::: "memory"); \
    asm volatile("barrier.cluster.wait.aligned;" ::: "memory"); \
} while (0)

// ---------------------------------------------------------------------------
// Input projection with fused embedding gather (bf16 tensor cores):
//   gx[dir][s][b][n] = sum_e embed[row][e] * W_ih[n][e] + b_ih[n] + b_hh[n]
// Block tile: 64 (batch rows at fixed s) x 128 (gate cols), K=256 smem-resident.
// ---------------------------------------------------------------------------
#define INP_SMEM ((64 + 128) * 132 * 4)

__global__ __launch_bounds__(256) void gemm_inproj_tc(
    const float* __restrict__ embed,
    const float* __restrict__ Wf, const float* __restrict__ Wb,
    const float* __restrict__ bih_f, const float* __restrict__ bhh_f,
    const float* __restrict__ bih_b, const float* __restrict__ bhh_b,
    const int* __restrict__ sent, const int* __restrict__ lens)
{
    extern __shared__ uint32_t smw[];
    uint32_t* au = smw;              // A: 64 rows x 132 words (bf16x2)
    uint32_t* wu = smw + 64 * 132;   // W: 128 rows x 132 words
    __shared__ int rowid[64];

    const int dir = blockIdx.z;
    const int m0 = blockIdx.x * 64;
    const int n0 = blockIdx.y * 128;
    const int s  = m0 >> 8;
    const int bf = m0 & 255;
    if (s >= lens[bf]) return;   // lengths sorted desc

    const int tid = threadIdx.x;
    if (tid < 64) {
        int b = bf + tid;
        int len = lens[b];
        int ss = (dir == 1 && s < len) ? (len - 1 - s) : s;
        rowid[tid] = sent[b * SS + ss];
    }
    __syncthreads();

    for (int idx = tid; idx < 64 * 64; idx += 256) {
        int r = idx >> 6, q4 = idx & 63;
        float4 v = *(const float4*)(embed + (size_t)rowid[r] * EE + q4 * 4);
        au[r * 132 + q4 * 2]     = pack_bf16(v.x, v.y);
        au[r * 132 + q4 * 2 + 1] = pack_bf16(v.z, v.w);
    }
    const float* __restrict__ W = dir ? Wb : Wf;
    for (int idx = tid; idx < 128 * 64; idx += 256) {
        int c = idx >> 6, q4 = idx & 63;
        float4 w = *(const float4*)(W + (size_t)(n0 + c) * EE + q4 * 4);
        wu[c * 132 + q4 * 2]     = pack_bf16(w.x, w.y);
        wu[c * 132 + q4 * 2 + 1] = pack_bf16(w.z, w.w);
    }
    __syncthreads();

    const int lane = tid & 31, wid = tid >> 5;
    const int wm = wid & 3, wn = wid >> 2;
    const int lr = lane >> 2, lc = lane & 3;

    float acc[8][4];
    #pragma unroll
    for (int i = 0; i < 8; i++)
        #pragma unroll
        for (int j = 0; j < 4; j++) acc[i][j] = 0.f;

    const int arow = (wm * 16 + lr) * 132;

    #pragma unroll 4
    for (int kc = 0; kc < 128; kc += 8) {   // word index; 8 words = 16 k
        uint32_t a[4];
        a[0] = au[arow + kc + lc];
        a[1] = au[arow + 8 * 132 + kc + lc];
        a[2] = au[arow + kc + 4 + lc];
        a[3] = au[arow + 8 * 132 + kc + 4 + lc];
        #pragma unroll
        for (int nf = 0; nf < 8; nf++) {
            int cc = wn * 64 + nf * 8 + lr;
            uint32_t b[2];
            b[0] = wu[cc * 132 + kc + lc];
            b[1] = wu[cc * 132 + kc + 4 + lc];
            mma_bf16(acc[nf], a, b);
        }
    }

    const float* bi = dir ? bih_b : bih_f;
    const float* bh = dir ? bhh_b : bhh_f;
    float* gxp = &g_gx[dir][0][0][0];
    const int row = m0 + wm * 16 + lr;
    #pragma unroll
    for (int nf = 0; nf < 8; nf++) {
        int n = n0 + wn * 64 + nf * 8 + lc * 2;
        float b0v = bi[n] + bh[n];
        float b1v = bi[n + 1] + bh[n + 1];
        *(float2*)(gxp + (size_t)row * GG + n) =
            make_float2(acc[nf][0] + b0v, acc[nf][1] + b1v);
        *(float2*)(gxp + (size_t)(row + 8) * GG + n) =
            make_float2(acc[nf][2] + b0v, acc[nf][3] + b1v);
    }
}

// ---------------------------------------------------------------------------
// Persistent bidirectional LSTM: clusters of 8 CTAs, one cluster per
// (dir, 32-batch tile) -> 128 CTAs total. Each CTA owns 128 gate cols
// (4 gates x 32 j). Per step: 32x128x256 bf16 MMA, gate epilogue for its
// 32 j-cols, bf16 h-slice broadcast into all 8 cluster CTAs' smem via DSMEM
// (double-buffered). One cluster.sync per step. gx LDGs issued before the
// MMA loop to hide DRAM latency.
// ---------------------------------------------------------------------------
#define LSTM_ST_WORDS (32 * 132)           // fp32 staging [32][132]
#define LSTM_WS_WORDS (128 * 132)          // bf16x2 weights [128 cols][132]
#define LSTM_HS_WORDS (2 * 32 * 132)       // bf16x2 h, double-buffered
#define LSTM_SMEM ((LSTM_ST_WORDS + LSTM_WS_WORDS + LSTM_HS_WORDS) * 4)

__global__ __launch_bounds__(256, 1) __cluster_dims__(8, 1, 1)
void lstm_persist(
    const float* __restrict__ Whh_f, const float* __restrict__ Whh_b,
    const int* __restrict__ lens)
{
    extern __shared__ float smf[];
    float* st = smf;                                    // [32][132] fp32
    uint32_t* wsu = (uint32_t*)(smf + LSTM_ST_WORDS);   // [128][132] bf16x2
    uint32_t* hsu = wsu + LSTM_WS_WORDS;                // [2][32][132] bf16x2

    const int tid = threadIdx.x;
    const int jt  = blockIdx.x;          // cluster rank, 0..7 -> j-cols jt*32..+32
    const int dir = blockIdx.y >> 3;
    const int mb  = blockIdx.y & 7;
    const int b0  = mb * 32;
    const int lenmax = lens[b0];         // same for whole cluster

    // Load bf16 weights once. Local col c (0..127): gate g=c>>5, j=jt*32+(c&31)
    const float* __restrict__ W = dir ? Whh_b : Whh_f;
    for (int idx = tid; idx < 128 * 64; idx += 256) {
        int c = idx >> 6, q4 = idx & 63;
        int n = ((c >> 5) << 8) + jt * 32 + (c & 31);
        float4 w = *(const float4*)(W + (size_t)n * HH + q4 * 4);
        wsu[c * 132 + q4 * 2]     = pack_bf16(w.x, w.y);
        wsu[c * 132 + q4 * 2 + 1] = pack_bf16(w.z, w.w);
    }
    for (int idx = tid; idx < LSTM_HS_WORDS; idx += 256) hsu[idx] = 0u;

    const int lane = tid & 31, w = tid >> 5;
    const int lr = lane >> 2, lc = lane & 3;
    const int bl  = tid >> 3;            // epilogue batch row 0..31
    const int jl4 = (tid & 7) * 4;       // epilogue j group (4 cols)

    float creg[4] = {0.f, 0.f, 0.f, 0.f};

    const float* gxbase = &g_gx[dir][0][0][0];
    float* hbase = &g_h[dir][0][0][0];
    const uint32_t hs_base = smem_u32(hsu);

    // peers must finish zero-init before anyone's step-0 remote writes land
    CLUSTER_SYNC();

    for (int s = 0; s < lenmax; s++) {
        // --- prefetch this step's gx (independent of h; hides under MMA) ---
        const float* gxr = gxbase + (size_t)s * BB * GG
                         + (size_t)(b0 + bl) * GG + jt * 32 + jl4;
        float4 x0 = *(const float4*)(gxr);
        float4 x1 = *(const float4*)(gxr + 256);
        float4 x2 = *(const float4*)(gxr + 512);
        float4 x3 = *(const float4*)(gxr + 768);

        const uint32_t* hb = hsu + (s & 1) * (32 * 132);

        float acc[2][2][4];
        #pragma unroll
        for (int mf = 0; mf < 2; mf++)
            #pragma unroll
            for (int nf = 0; nf < 2; nf++)
                #pragma unroll
                for (int q = 0; q < 4; q++) acc[mf][nf][q] = 0.f;

        #pragma unroll 4
        for (int kc = 0; kc < 128; kc += 8) {   // 8 words = 16 k
            uint32_t a0[4], a1[4];
            a0[0] = hb[lr * 132 + kc + lc];
            a0[1] = hb[(lr + 8) * 132 + kc + lc];
            a0[2] = hb[lr * 132 + kc + 4 + lc];
            a0[3] = hb[(lr + 8) * 132 + kc + 4 + lc];
            a1[0] = hb[(16 + lr) * 132 + kc + lc];
            a1[1] = hb[(24 + lr) * 132 + kc + lc];
            a1[2] = hb[(16 + lr) * 132 + kc + 4 + lc];
            a1[3] = hb[(24 + lr) * 132 + kc + 4 + lc];
            #pragma unroll
            for (int nf = 0; nf < 2; nf++) {
                int cc = w * 16 + nf * 8 + lr;
                uint32_t b[2];
                b[0] = wsu[cc * 132 + kc + lc];
                b[1] = wsu[cc * 132 + kc + 4 + lc];
                mma_bf16(acc[0][nf], a0, b);
                mma_bf16(acc[1][nf], a1, b);
            }
        }

        // stage GEMM result: st[batch 0..31][local col 0..127]
        #pragma unroll
        for (int mf = 0; mf < 2; mf++)
            #pragma unroll
            for (int nf = 0; nf < 2; nf++) {
                int row = mf * 16 + lr, col = w * 16 + nf * 8 + lc * 2;
                *(float2*)&st[row * 132 + col] =
                    make_float2(acc[mf][nf][0], acc[mf][nf][1]);
                *(float2*)&st[(row + 8) * 132 + col] =
                    make_float2(acc[mf][nf][2], acc[mf][nf][3]);
            }
        __syncthreads();

        // epilogue: thread handles batch bl, j cols jl4..jl4+3 (4 gates each)
        float4 v0 = *(const float4*)&st[bl * 132 +       jl4];
        float4 v1 = *(const float4*)&st[bl * 132 +  32 + jl4];
        float4 v2 = *(const float4*)&st[bl * 132 +  64 + jl4];
        float4 v3 = *(const float4*)&st[bl * 132 +  96 + jl4];
        float gi[4] = {v0.x + x0.x, v0.y + x0.y, v0.z + x0.z, v0.w + x0.w};
        float gf[4] = {v1.x + x1.x, v1.y + x1.y, v1.z + x1.z, v1.w + x1.w};
        float gg[4] = {v2.x + x2.x, v2.y + x2.y, v2.z + x2.z, v2.w + x2.w};
        float go[4] = {v3.x + x3.x, v3.y + x3.y, v3.z + x3.z, v3.w + x3.w};

        float hn[4];
        #pragma unroll
        for (int k = 0; k < 4; k++) {
            float si = 1.f / (1.f + __expf(-gi[k]));
            float sf = 1.f / (1.f + __expf(-gf[k]));
            float so = 1.f / (1.f + __expf(-go[k]));
            float cn = sf * creg[k] + si * tanhf(gg[k]);
            creg[k] = cn;
            hn[k] = so * tanhf(cn);
        }

        // fp32 h to gmem for emit
        float* hd = hbase + (size_t)(s + 1) * BB * HH
                  + (size_t)(b0 + bl) * HH + jt * 32 + jl4;
        *(float4*)hd = make_float4(hn[0], hn[1], hn[2], hn[3]);

        // bf16 h broadcast into all 8 cluster CTAs' next-step buffer
        uint32_t pw0 = pack_bf16(hn[0], hn[1]);
        uint32_t pw1 = pack_bf16(hn[2], hn[3]);
        unsigned long long pv = ((unsigned long long)pw1 << 32) | pw0;
        uint32_t woff = (uint32_t)(((s + 1) & 1) * (32 * 132)
                      + bl * 132 + jt * 16 + (jl4 >> 1));
        uint32_t baddr = hs_base + woff * 4;
        #pragma unroll
        for (int r = 0; r < 8; r++) {
            uint32_t ra;
            asm("mapa.shared::cluster.u32 %0, %1, %2;" : "=r"(ra) : "r"(baddr), "r"(r));
            asm volatile("st.shared::cluster.u64 [%0], %1;" :: "r"(ra), "l"(pv) : "memory");
        }

        // release our writes / acquire peers' (also acts as CTA barrier)
        CLUSTER_SYNC();
    }
}

// ---------------------------------------------------------------------------
// emit via bf16 MMA (fp32 accumulate):
// emit[b][s][t] = b_out[t] + h_f[s].Wout[t][0:256] + h_b[len-1-s].Wout[t][256:512]
// Block: one b x 32 s-rows. M=32, N=32, K=512. 8 warps, one (m16,n8) pair each.
// ---------------------------------------------------------------------------
#define EMIT_SMEM (2 * 32 * 260 * 4)

__global__ __launch_bounds__(256) void emit_kernel(
    const float* __restrict__ Wout, const float* __restrict__ bout,
    const int* __restrict__ lens)
{
    extern __shared__ uint32_t es[];
    uint32_t* hbw = es;            // [32 s][260 words] bf16x2
    uint32_t* wbw = es + 32 * 260; // [32 t][260 words] bf16x2

    int b = blockIdx.x;
    int s0 = blockIdx.y * 32;
    int len = lens[b];
    if (s0 >= len) return;

    int tid = threadIdx.x;
    for (int idx = tid; idx < 32 * 128; idx += 256) {
        int sl = idx >> 7, q4 = idx & 127;
        int s = s0 + sl;
        float4 v = make_float4(0.f, 0.f, 0.f, 0.f);
        if (s < len) {
            int q = q4 * 4;
            if (q < 256) v = *(const float4*)&g_h[0][s + 1][b][q];
            else         v = *(const float4*)&g_h[1][len - s][b][q - 256];
        }
        hbw[sl * 260 + q4 * 2]     = pack_bf16(v.x, v.y);
        hbw[sl * 260 + q4 * 2 + 1] = pack_bf16(v.z, v.w);
    }
    for (int idx = tid; idx < 32 * 128; idx += 256) {
        int t = idx >> 7, q4 = idx & 127;
        float4 wv = *(const float4*)&Wout[t * 512 + q4 * 4];
        wbw[t * 260 + q4 * 2]     = pack_bf16(wv.x, wv.y);
        wbw[t * 260 + q4 * 2 + 1] = pack_bf16(wv.z, wv.w);
    }
    __syncthreads();

    const int lane = tid & 31, w = tid >> 5;
    const int m2 = w >> 2, n4 = w & 3;
    const int lr = lane >> 2, lc = lane & 3;

    float acc[4] = {0.f, 0.f, 0.f, 0.f};
    const int arow = (m2 * 16 + lr) * 260;
    const int brow = (n4 * 8 + lr) * 260;

    #pragma unroll 8
    for (int kc = 0; kc < 256; kc += 8) {
        uint32_t a[4], bb[2];
        a[0] = hbw[arow + kc + lc];
        a[1] = hbw[arow + 8 * 260 + kc + lc];
        a[2] = hbw[arow + kc + 4 + lc];
        a[3] = hbw[arow + 8 * 260 + kc + 4 + lc];
        bb[0] = wbw[brow + kc + lc];
        bb[1] = wbw[brow + kc + 4 + lc];
        mma_bf16(acc, a, bb);
    }

    int t = n4 * 8 + lc * 2;
    float b0v = bout[t], b1v = bout[t + 1];
    int r0 = s0 + m2 * 16 + lr;
    if (r0 < len)
        *(float2*)&g_emit[b][r0][t] = make_float2(acc[0] + b0v, acc[1] + b1v);
    if (r0 + 8 < len)
        *(float2*)&g_emit[b][r0 + 8][t] = make_float2(acc[2] + b0v, acc[3] + b1v);
}

// ---------------------------------------------------------------------------
// Per-batch CRF, one warp per b. Forward recursion refactored:
//   alpha_j' = M + log( sum_i exp(alpha_i - M) * E_ij ) + emit_j,
// E = exp(transition) held in registers -> 32 SHFL+FFMA replace 32 MUFU.
// ---------------------------------------------------------------------------
__global__ void crf_kernel(
    const float* __restrict__ trans,
    const int* __restrict__ tags,
    const int* __restrict__ lens,
    float* __restrict__ out)
{
    int b = blockIdx.x;
    int j = threadIdx.x;   // 0..31
    __shared__ float tr[32][33];

    int len = lens[b];
    for (int idx = j; idx < 1024; idx += 32)
        tr[idx >> 5][idx & 31] = trans[idx];
    __syncwarp();

    float E[32];
    #pragma unroll
    for (int i = 0; i < 32; i++) E[i] = __expf(tr[i][j]);

    const int* tg = tags + b * SS;
    const float* em = &g_emit[b][0][0];

    // real path score
    float rs = 0.f;
    for (int s = j; s < len; s += 32) {
        int t1 = tg[s];
        float v = em[s * 32 + t1];
        if (s > 0) v += tr[tg[s - 1]][t1];
        rs += v;
    }
    #pragma unroll
    for (int o = 16; o; o >>= 1) rs += __shfl_xor_sync(0xffffffffu, rs, o);

    // forward recursion
    float alpha = em[j];
    float M = alpha;
    #pragma unroll
    for (int o = 16; o; o >>= 1) M = fmaxf(M, __shfl_xor_sync(0xffffffffu, M, o));
    float beta = __expf(alpha - M);

    for (int s = 1; s < len; s++) {
        float dot = 0.f;
        #pragma unroll
        for (int i = 0; i < 32; i++)
            dot = fmaf(__shfl_sync(0xffffffffu, beta, i), E[i], dot);
        alpha = M + __logf(dot) + em[s * 32 + j];
        float m2 = alpha;
        #pragma unroll
        for (int o = 16; o; o >>= 1) m2 = fmaxf(m2, __shfl_xor_sync(0xffffffffu, m2, o));
        M = m2;
        beta = __expf(alpha - M);
    }

    float e = beta;
    #pragma unroll
    for (int o = 16; o; o >>= 1) e += __shfl_xor_sync(0xffffffffu, e, o);
    float logz = M + __logf(e);
    if (j == 0) out[b] = logz - rs;
}

// ---------------------------------------------------------------------------
extern "C" void kernel_launch(void* const* d_in, const int* in_sizes, int n_in,
                              void* d_out, int out_size)
{
    const float* embed = (const float*)d_in[0];
    const float* Wih_f = (const float*)d_in[1];
    const float* Whh_f = (const float*)d_in[2];
    const float* bih_f = (const float*)d_in[3];
    const float* bhh_f = (const float*)d_in[4];
    const float* Wih_b = (const float*)d_in[5];
    const float* Whh_b = (const float*)d_in[6];
    const float* bih_b = (const float*)d_in[7];
    const float* bhh_b = (const float*)d_in[8];
    const float* Wout  = (const float*)d_in[9];
    const float* bout  = (const float*)d_in[10];
    const float* trans = (const float*)d_in[11];
    const int* sent = (const int*)d_in[12];
    const int* tags = (const int*)d_in[13];
    const int* lens = (const int*)d_in[14];
    float* out = (float*)d_out;

    cudaFuncSetAttribute(gemm_inproj_tc,
                         cudaFuncAttributeMaxDynamicSharedMemorySize, INP_SMEM);
    cudaFuncSetAttribute(lstm_persist,
                         cudaFuncAttributeMaxDynamicSharedMemorySize, LSTM_SMEM);
    cudaFuncSetAttribute(emit_kernel,
                         cudaFuncAttributeMaxDynamicSharedMemorySize, EMIT_SMEM);

    dim3 g1(2048, 8, 2);
    gemm_inproj_tc<<<g1, 256, INP_SMEM>>>(embed, Wih_f, Wih_b,
                                          bih_f, bhh_f, bih_b, bhh_b, sent, lens);

    dim3 gl(8, 16);
    lstm_persist<<<gl, 256, LSTM_SMEM>>>(Whh_f, Whh_b, lens);

    dim3 ge(256, 16);
    emit_kernel<<<ge, 256, EMIT_SMEM>>>(Wout, bout, lens);

    crf_kernel<<<256, 32>>>(trans, tags, lens, out);
}